// round 10
// baseline (speedup 1.0000x reference)
#include <cuda_runtime.h>
#include <math.h>
#include <stdint.h>

#define BNUM  50
#define E0    600000
#define FIN   256
#define NH    128
#define N0MAX 100000
#define N1MAX 80000

// ---------------- scratch (device globals; no allocs allowed) ----------------
__device__ float g_h[N0MAX * NH];        // GEMM output h = x @ W
__device__ float g_xa[N0MAX * NH];       // conv output x' (post-relu)
__device__ float g_xb[N1MAX * NH];       // pooled features
__device__ float g_hs[N0MAX];            // score projection h_s = x' @ Ws
__device__ int   g_deg0[N0MAX], g_deg1[N0MAX], g_deg2[N0MAX];
__device__ int   g_map0[N0MAX], g_map1[N0MAX], g_map2[N0MAX];
__device__ float g_dis[N0MAX];           // rsqrt(deg+1)
__device__ float g_dinv[N0MAX];          // 1/(deg+1)
__device__ int   g_rowptr[N0MAX + 1];
__device__ int   g_cursor[N0MAX];
__device__ int   g_exsc[N0MAX];
__device__ int   g_bsum[128];
__device__ int   g_csr[E0];              // src ids bucketed by dst
__device__ int   g_esrc0[E0], g_edst0[E0];
__device__ int   g_esrc1[E0], g_edst1[E0];
__device__ float g_x123[BNUM * 2 * NH];  // x1+x2+x3 accumulator
__device__ int   g_cnt[4];               // [0]=E stage1, [1]=E after pool1, [2]=after pool2

// ---------------- f32x2 packed helpers ----------------
__device__ __forceinline__ unsigned long long splat2(float x) {
    unsigned long long d;
    asm("mov.b64 %0, {%1, %1};" : "=l"(d) : "r"(__float_as_uint(x)));
    return d;
}
__device__ __forceinline__ void fma2(unsigned long long& acc,
                                     unsigned long long a, unsigned long long b) {
    asm("fma.rn.f32x2 %0, %1, %2, %0;" : "+l"(acc) : "l"(a), "l"(b));
}
__device__ __forceinline__ void unpack2(unsigned long long v, float& lo, float& hi) {
    uint32_t l, h;
    asm("mov.b64 {%0, %1}, %2;" : "=r"(l), "=r"(h) : "l"(v));
    lo = __uint_as_float(l); hi = __uint_as_float(h);
}

// ---------------- kernels ----------------
// one-shot init (runs each replay): zero deg buffers, -1 maps, zero x123, cnts
__global__ void k_init() {
    int i = blockIdx.x * blockDim.x + threadIdx.x;
    if (i < N0MAX) {
        g_deg0[i] = 0; g_deg1[i] = 0; g_deg2[i] = 0;
        g_map0[i] = -1; g_map1[i] = -1; g_map2[i] = -1;
    }
    if (i < BNUM * 2 * NH) g_x123[i] = 0.f;
    if (i == 0) { g_cnt[0] = E0; g_cnt[1] = 0; g_cnt[2] = 0; }
}

__global__ void k_count(const int* __restrict__ dst, const int* __restrict__ cnt,
                        int* __restrict__ deg) {
    int i = blockIdx.x * blockDim.x + threadIdx.x;
    if (i < *cnt) atomicAdd(&deg[dst[i]], 1);
}

// block-level scan via warp shuffles (+ fused degnorm)
__global__ void k_scan1(int N, const int* __restrict__ deg) {
    __shared__ int wsum[32];
    int tid = threadIdx.x;
    int i = blockIdx.x * 1024 + tid;
    int v = (i < N) ? deg[i] : 0;
    if (i < N) {
        float d = (float)v + 1.0f;
        g_dinv[i] = 1.0f / d;
        g_dis[i]  = rsqrtf(d);
    }
    int lane = tid & 31, wid = tid >> 5;
    int incl = v;
    #pragma unroll
    for (int off = 1; off < 32; off <<= 1) {
        int t = __shfl_up_sync(0xffffffffu, incl, off);
        if (lane >= off) incl += t;
    }
    if (lane == 31) wsum[wid] = incl;
    __syncthreads();
    if (wid == 0) {
        int w = wsum[lane];
        #pragma unroll
        for (int off = 1; off < 32; off <<= 1) {
            int t = __shfl_up_sync(0xffffffffu, w, off);
            if (lane >= off) w += t;
        }
        wsum[lane] = w;           // inclusive scan of warp sums
    }
    __syncthreads();
    int wpre = (wid > 0) ? wsum[wid - 1] : 0;
    if (i < N) g_exsc[i] = wpre + incl - v;
    if (tid == 1023) g_bsum[blockIdx.x] = wsum[31];
}

// scan finalize: each block prefixes bsums itself
__global__ void k_scan3(int N, const int* __restrict__ cnt) {
    __shared__ int pref;
    if (threadIdx.x == 0) {
        int s = 0, hb = blockIdx.x >> 2;   // 256*4 = 1024 idx per bsum entry
        for (int j = 0; j < hb; j++) s += g_bsum[j];
        pref = s;
    }
    __syncthreads();
    int i = blockIdx.x * blockDim.x + threadIdx.x;
    if (i < N) {
        int r = g_exsc[i] + pref;
        g_rowptr[i] = r;
        g_cursor[i] = r;
    }
    if (i == 0) g_rowptr[N] = *cnt;
}

__global__ void k_csr(const int* __restrict__ src, const int* __restrict__ dst,
                      const int* __restrict__ cnt) {
    int i = blockIdx.x * blockDim.x + threadIdx.x;
    if (i < *cnt) {
        int d = dst[i];
        int p = atomicAdd(&g_cursor[d], 1);
        g_csr[p] = src[i];
    }
}

// h = X @ W   (X: [N,F] row-major, W: [F,128] row-major) -> g_h
// BM=128, BN=128, BK=16, 256 threads, 8x8 tile, double-buffered, f32x2 packed FMA
__global__ __launch_bounds__(256, 2)
void k_gemm(const float* __restrict__ X, const float* __restrict__ W,
            int N, int F) {
    __shared__ float As[2][16 * 128];   // transposed: As[b][kk][row]
    __shared__ float Bs[2][16 * 128];   // Bs[b][kk][col]
    const int tid = threadIdx.x;
    const int tx = tid & 15, ty = tid >> 4;
    const int rowBase = blockIdx.x * 128;

    const int ar  = tid >> 1;
    const int ac0 = (tid & 1) * 2;
    const int br0 = tid >> 4;
    const int bc0 = (2 * tid) & 31;

    unsigned long long acc2[4][8];
    #pragma unroll
    for (int rp = 0; rp < 4; rp++)
        #pragma unroll
        for (int c = 0; c < 8; c++) acc2[rp][c] = 0ull;

    float4 va0, va1, vb0, vb1;

#define LDT(kt) do {                                                            \
    int grow = rowBase + ar;                                                    \
    if (grow < N) {                                                             \
        va0 = *(const float4*)&X[(size_t)grow * F + (kt) + ac0 * 4];            \
        va1 = *(const float4*)&X[(size_t)grow * F + (kt) + ac0 * 4 + 4];        \
    } else {                                                                    \
        va0 = make_float4(0.f, 0.f, 0.f, 0.f);                                  \
        va1 = make_float4(0.f, 0.f, 0.f, 0.f);                                  \
    }                                                                           \
    vb0 = *(const float4*)&W[(size_t)((kt) + br0) * 128 + bc0 * 4];             \
    vb1 = *(const float4*)&W[(size_t)((kt) + br0) * 128 + bc0 * 4 + 4];         \
} while (0)

#define STT(b) do {                                                             \
    As[b][(ac0 * 4 + 0) * 128 + ar] = va0.x;                                    \
    As[b][(ac0 * 4 + 1) * 128 + ar] = va0.y;                                    \
    As[b][(ac0 * 4 + 2) * 128 + ar] = va0.z;                                    \
    As[b][(ac0 * 4 + 3) * 128 + ar] = va0.w;                                    \
    As[b][(ac0 * 4 + 4) * 128 + ar] = va1.x;                                    \
    As[b][(ac0 * 4 + 5) * 128 + ar] = va1.y;                                    \
    As[b][(ac0 * 4 + 6) * 128 + ar] = va1.z;                                    \
    As[b][(ac0 * 4 + 7) * 128 + ar] = va1.w;                                    \
    *(float4*)&Bs[b][br0 * 128 + bc0 * 4]     = vb0;                            \
    *(float4*)&Bs[b][br0 * 128 + bc0 * 4 + 4] = vb1;                            \
} while (0)

    const int T = F >> 4;
    LDT(0);
    STT(0);
    __syncthreads();

    for (int t = 0; t < T; t++) {
        const int cur = t & 1;
        if (t + 1 < T) LDT((t + 1) * 16);
        #pragma unroll
        for (int kk = 0; kk < 16; kk++) {
            ulonglong2 a01 = *(const ulonglong2*)&As[cur][kk * 128 + ty * 8];
            ulonglong2 a23 = *(const ulonglong2*)&As[cur][kk * 128 + ty * 8 + 4];
            float4 b0 = *(const float4*)&Bs[cur][kk * 128 + tx * 8];
            float4 b1 = *(const float4*)&Bs[cur][kk * 128 + tx * 8 + 4];
            unsigned long long ap[4] = {a01.x, a01.y, a23.x, a23.y};
            unsigned long long bp[8];
            bp[0] = splat2(b0.x); bp[1] = splat2(b0.y);
            bp[2] = splat2(b0.z); bp[3] = splat2(b0.w);
            bp[4] = splat2(b1.x); bp[5] = splat2(b1.y);
            bp[6] = splat2(b1.z); bp[7] = splat2(b1.w);
            #pragma unroll
            for (int rp = 0; rp < 4; rp++)
                #pragma unroll
                for (int c = 0; c < 8; c++)
                    fma2(acc2[rp][c], ap[rp], bp[c]);
        }
        if (t + 1 < T) STT((t + 1) & 1);
        __syncthreads();
    }
#undef LDT
#undef STT

    #pragma unroll
    for (int rp = 0; rp < 4; rp++) {
        float lo[8], hi[8];
        #pragma unroll
        for (int c = 0; c < 8; c++) unpack2(acc2[rp][c], lo[c], hi[c]);
        int gr0 = rowBase + ty * 8 + rp * 2;
        if (gr0 < N) {
            *(float4*)&g_h[(size_t)gr0 * NH + tx * 8] =
                make_float4(lo[0], lo[1], lo[2], lo[3]);
            *(float4*)&g_h[(size_t)gr0 * NH + tx * 8 + 4] =
                make_float4(lo[4], lo[5], lo[6], lo[7]);
        }
        if (gr0 + 1 < N) {
            *(float4*)&g_h[(size_t)(gr0 + 1) * NH + tx * 8] =
                make_float4(hi[0], hi[1], hi[2], hi[3]);
            *(float4*)&g_h[(size_t)(gr0 + 1) * NH + tx * 8 + 4] =
                make_float4(hi[4], hi[5], hi[6], hi[7]);
        }
    }
}

// warp per node: x' = relu(sum_in h[src]*dis[src]*dis[n] + h[n]/deg + b); also h_s = x' . Ws
__global__ void k_agg(const float* __restrict__ b, const float* __restrict__ Ws, int N) {
    int gid = blockIdx.x * blockDim.x + threadIdx.x;
    int w = gid >> 5, lane = gid & 31;
    if (w >= N) return;
    int beg = g_rowptr[w], end = g_rowptr[w + 1];
    float dn = g_dis[w];
    float4 acc = make_float4(0.f, 0.f, 0.f, 0.f);
    int e = beg;
    for (; e + 2 <= end; e += 2) {            // unroll x2 for MLP
        int s0 = g_csr[e], s1 = g_csr[e + 1];
        float nm0 = g_dis[s0] * dn, nm1 = g_dis[s1] * dn;
        float4 h0 = *(const float4*)&g_h[s0 * NH + lane * 4];
        float4 h1 = *(const float4*)&g_h[s1 * NH + lane * 4];
        acc.x += h0.x * nm0 + h1.x * nm1;
        acc.y += h0.y * nm0 + h1.y * nm1;
        acc.z += h0.z * nm0 + h1.z * nm1;
        acc.w += h0.w * nm0 + h1.w * nm1;
    }
    if (e < end) {
        int s = g_csr[e];
        float nm = g_dis[s] * dn;
        float4 hv = *(const float4*)&g_h[s * NH + lane * 4];
        acc.x += hv.x * nm; acc.y += hv.y * nm;
        acc.z += hv.z * nm; acc.w += hv.w * nm;
    }
    float di = g_dinv[w];
    float4 hw = *(const float4*)&g_h[w * NH + lane * 4];
    float4 bb = *(const float4*)&b[lane * 4];
    float4 o;
    o.x = fmaxf(acc.x + hw.x * di + bb.x, 0.f);
    o.y = fmaxf(acc.y + hw.y * di + bb.y, 0.f);
    o.z = fmaxf(acc.z + hw.z * di + bb.z, 0.f);
    o.w = fmaxf(acc.w + hw.w * di + bb.w, 0.f);
    *(float4*)&g_xa[w * NH + lane * 4] = o;
    float4 wv = *(const float4*)&Ws[lane * 4];
    float d = o.x * wv.x + o.y * wv.y + o.z * wv.z + o.w * wv.w;
    #pragma unroll
    for (int off = 16; off; off >>= 1) d += __shfl_xor_sync(0xffffffffu, d, off);
    if (lane == 0) g_hs[w] = d;
}

// block per graph: fused score-aggregation (sagg), bitonic sort, pool + readout
__launch_bounds__(1024)
__global__ void k_topk(int n, int k, int* __restrict__ map,
                       const float* __restrict__ bs) {
    __shared__ float ss[2048];
    __shared__ int   si[2048];
    __shared__ float st[2048];           // tanh(sorted score)
    int g = blockIdx.x, tid = threadIdx.x;
    float bias = bs[0];
    // fused sagg: score for this graph's nodes
    for (int j = tid; j < 2048; j += 1024) {
        float sc = -3.402823466e38f;
        if (j < n) {
            int i = g * n + j;
            int beg = g_rowptr[i], end = g_rowptr[i + 1];
            float s = 0.f;
            for (int e = beg; e < end; e++) {
                int u = g_csr[e];
                s += g_hs[u] * g_dis[u];
            }
            sc = s * g_dis[i] + g_hs[i] * g_dinv[i] + bias;
        }
        ss[j] = sc; si[j] = j;
    }
    __syncthreads();
    for (int kk = 2; kk <= 2048; kk <<= 1) {
        for (int jj = kk >> 1; jj > 0; jj >>= 1) {
            for (int i = tid; i < 2048; i += 1024) {
                int l = i ^ jj;
                if (l > i) {
                    float si_ = ss[i], sl_ = ss[l];
                    int ii_ = si[i], il_ = si[l];
                    bool before = (si_ > sl_) || (si_ == sl_ && ii_ < il_);
                    bool asc = ((i & kk) == 0);
                    if (asc != before) {
                        ss[i] = sl_; ss[l] = si_;
                        si[i] = il_; si[l] = ii_;
                    }
                }
            }
            __syncthreads();
        }
    }
    for (int j = tid; j < k; j += 1024) {
        int p = g * n + si[j];
        map[p] = g * k + j;
        st[j] = tanhf(ss[j]);
    }
    __syncthreads();
    // fused pool + readout: 8 node-groups x 128 features
    int f = tid & 127, grp = tid >> 7;
    float mx = -3.402823466e38f, sm = 0.f;
    for (int i = grp; i < k; i += 8) {
        int p = g * n + si[i];
        float v = g_xa[p * NH + f] * st[i];
        g_xb[(size_t)(g * k + i) * NH + f] = v;
        mx = fmaxf(mx, v); sm += v;
    }
    __syncthreads();
    ss[tid] = mx;
    ss[1024 + tid] = sm;
    __syncthreads();
    if (tid < 128) {
        float m = ss[tid], s2 = ss[1024 + tid];
        #pragma unroll
        for (int g2 = 1; g2 < 8; g2++) {
            m = fmaxf(m, ss[g2 * 128 + tid]);
            s2 += ss[1024 + g2 * 128 + tid];
        }
        g_x123[g * (2 * NH) + tid]      += m;
        g_x123[g * (2 * NH) + NH + tid] += s2 / (float)k;
    }
}

// filter + fused degree count; WARP-AGGREGATED counter atomic
// (single-address atomicAdd serializes ~1cyc/op at the LTS; ballot+popc cuts
//  same-address traffic by 32x: 371K atomics -> 12K)
__global__ void k_filtcnt(const int* __restrict__ src, const int* __restrict__ dst,
                          const int* __restrict__ cnt, const int* __restrict__ map,
                          int* __restrict__ nsrc, int* __restrict__ ndst,
                          int* __restrict__ ncnt, int* __restrict__ deg) {
    int i = blockIdx.x * blockDim.x + threadIdx.x;
    int lane = threadIdx.x & 31;
    int a = -1, b = -1;
    bool valid = false;
    if (i < *cnt) {
        a = map[src[i]];
        b = map[dst[i]];
        valid = (a >= 0 && b >= 0);
    }
    unsigned m = __ballot_sync(0xffffffffu, valid);
    if (m == 0) return;
    int leader = __ffs(m) - 1;
    int base = 0;
    if (lane == leader) base = atomicAdd(ncnt, __popc(m));
    base = __shfl_sync(0xffffffffu, base, leader);
    if (valid) {
        int pos = base + __popc(m & ((1u << lane) - 1u));
        nsrc[pos] = a;
        ndst[pos] = b;
        atomicAdd(&deg[b], 1);
    }
}

__global__ void k_final(const float* __restrict__ Wl, const float* __restrict__ bl,
                        float* __restrict__ out) {
    int g = blockIdx.x, o = threadIdx.x;
    float acc = bl[o];
    #pragma unroll 4
    for (int f = 0; f < 2 * NH; f++)
        acc = fmaf(g_x123[g * (2 * NH) + f], Wl[f * NH + o], acc);
    out[g * NH + o] = fmaxf(acc, 0.f);
}

// ---------------- host driver ----------------
extern "C" void kernel_launch(void* const* d_in, const int* in_sizes, int n_in,
                              void* d_out, int out_size) {
    static cudaStream_t s2 = nullptr;
    static cudaEvent_t evF = nullptr, evJ = nullptr;
    if (!s2) {
        cudaStreamCreateWithFlags(&s2, cudaStreamNonBlocking);
        cudaEventCreateWithFlags(&evF, cudaEventDisableTiming);
        cudaEventCreateWithFlags(&evJ, cudaEventDisableTiming);
    }

    const float* x   = (const float*)d_in[0];
    const float* W1  = (const float*)d_in[1];
    const float* b1  = (const float*)d_in[2];
    const float* Ws1 = (const float*)d_in[3];
    const float* bs1 = (const float*)d_in[4];
    const float* W2  = (const float*)d_in[5];
    const float* b2  = (const float*)d_in[6];
    const float* Ws2 = (const float*)d_in[7];
    const float* bs2 = (const float*)d_in[8];
    const float* W3  = (const float*)d_in[9];
    const float* b3  = (const float*)d_in[10];
    const float* Ws3 = (const float*)d_in[11];
    const float* bs3 = (const float*)d_in[12];
    const float* Wl  = (const float*)d_in[13];
    const float* bl  = (const float*)d_in[14];
    const int*   ei  = (const int*)d_in[15];
    float* out = (float*)d_out;

    int *p_es0, *p_ed0, *p_es1, *p_ed1, *p_cnt;
    int *p_deg0, *p_deg1, *p_deg2, *p_map0, *p_map1, *p_map2;
    float* p_xb;
    cudaGetSymbolAddress((void**)&p_es0, g_esrc0);
    cudaGetSymbolAddress((void**)&p_ed0, g_edst0);
    cudaGetSymbolAddress((void**)&p_es1, g_esrc1);
    cudaGetSymbolAddress((void**)&p_ed1, g_edst1);
    cudaGetSymbolAddress((void**)&p_cnt, g_cnt);
    cudaGetSymbolAddress((void**)&p_deg0, g_deg0);
    cudaGetSymbolAddress((void**)&p_deg1, g_deg1);
    cudaGetSymbolAddress((void**)&p_deg2, g_deg2);
    cudaGetSymbolAddress((void**)&p_map0, g_map0);
    cudaGetSymbolAddress((void**)&p_map1, g_map1);
    cudaGetSymbolAddress((void**)&p_map2, g_map2);
    cudaGetSymbolAddress((void**)&p_xb,  g_xb);

    const int EB = (E0 + 255) / 256;

    k_init<<<(N0MAX + 255) / 256, 256>>>();

    // ================= stage 1: N=100000, F=256, n=2000, k=1600 =================
    {
        const int Nin = 100000, n = 2000, kk = 1600;
        int nb = (Nin + 1023) / 1024;
        cudaEventRecord(evF, 0);
        cudaStreamWaitEvent(s2, evF, 0);
        k_count<<<EB, 256>>>(ei + E0, p_cnt + 0, p_deg0);
        k_scan1<<<nb, 1024>>>(Nin, p_deg0);
        k_gemm<<<(Nin + 127) / 128, 256, 0, s2>>>(x, W1, Nin, FIN);  // submit idx 3
        cudaEventRecord(evJ, s2);
        k_scan3<<<(Nin + 255) / 256, 256>>>(Nin, p_cnt + 0);
        k_csr<<<EB, 256>>>(ei, ei + E0, p_cnt + 0);
        cudaStreamWaitEvent(0, evJ, 0);
        k_agg<<<(Nin * 32 + 255) / 256, 256>>>(b1, Ws1, Nin);
        k_topk<<<BNUM, 1024>>>(n, kk, p_map0, bs1);
    }

    // ================= stage 2: N=80000, F=128, n=1600, k=1280 =================
    {
        const int Nin = 80000, n = 1600, kk = 1280;
        int nb = (Nin + 1023) / 1024;
        cudaEventRecord(evF, 0);                    // after topk1: g_xb ready
        cudaStreamWaitEvent(s2, evF, 0);
        k_gemm<<<(Nin + 127) / 128, 256, 0, s2>>>(p_xb, W2, Nin, NH);
        cudaEventRecord(evJ, s2);
        k_filtcnt<<<EB, 256>>>(ei, ei + E0, p_cnt + 0, p_map0,
                               p_es0, p_ed0, p_cnt + 1, p_deg1);
        k_scan1<<<nb, 1024>>>(Nin, p_deg1);
        k_scan3<<<(Nin + 255) / 256, 256>>>(Nin, p_cnt + 1);
        k_csr<<<EB, 256>>>(p_es0, p_ed0, p_cnt + 1);
        cudaStreamWaitEvent(0, evJ, 0);
        k_agg<<<(Nin * 32 + 255) / 256, 256>>>(b2, Ws2, Nin);
        k_topk<<<BNUM, 1024>>>(n, kk, p_map1, bs2);
    }

    // ================= stage 3: N=64000, F=128, n=1280, k=1024 =================
    {
        const int Nin = 64000, n = 1280, kk = 1024;
        int nb = (Nin + 1023) / 1024;
        cudaEventRecord(evF, 0);
        cudaStreamWaitEvent(s2, evF, 0);
        k_gemm<<<(Nin + 127) / 128, 256, 0, s2>>>(p_xb, W3, Nin, NH);
        cudaEventRecord(evJ, s2);
        k_filtcnt<<<EB, 256>>>(p_es0, p_ed0, p_cnt + 1, p_map1,
                               p_es1, p_ed1, p_cnt + 2, p_deg2);
        k_scan1<<<nb, 1024>>>(Nin, p_deg2);
        k_scan3<<<(Nin + 255) / 256, 256>>>(Nin, p_cnt + 2);
        k_csr<<<EB, 256>>>(p_es1, p_ed1, p_cnt + 2);
        cudaStreamWaitEvent(0, evJ, 0);
        k_agg<<<(Nin * 32 + 255) / 256, 256>>>(b3, Ws3, Nin);
        k_topk<<<BNUM, 1024>>>(n, kk, p_map2, bs3);
    }

    k_final<<<BNUM, NH>>>(Wl, bl, out);
}

// round 12
// speedup vs baseline: 1.1461x; 1.1461x over previous
#include <cuda_runtime.h>
#include <math.h>
#include <stdint.h>

#define BNUM  50
#define E0    600000
#define FIN   256
#define NH    128
#define N0MAX 100000
#define N1MAX 80000

// ---------------- scratch (device globals; no allocs allowed) ----------------
__device__ float g_h[N0MAX * NH];        // GEMM output h = x @ W
__device__ float g_xa[N0MAX * NH];       // conv output x' (post-relu)
__device__ float g_xb[N1MAX * NH];       // pooled features
__device__ float g_hs[N0MAX];            // score projection h_s = x' @ Ws
__device__ int   g_deg0[N0MAX], g_deg1[N0MAX], g_deg2[N0MAX];
__device__ int   g_map0[N0MAX], g_map1[N0MAX], g_map2[N0MAX];
__device__ float g_dis[N0MAX];           // rsqrt(deg+1)
__device__ float g_dinv[N0MAX];          // 1/(deg+1)
__device__ int   g_rowptr[N0MAX + 1];
__device__ int   g_cursor[N0MAX];
__device__ int   g_exsc[N0MAX];
__device__ int   g_bsum[128];
__device__ int   g_csr[E0];              // src ids bucketed by dst
__device__ int   g_esrc0[E0], g_edst0[E0];
__device__ int   g_esrc1[E0], g_edst1[E0];
__device__ float g_x123[BNUM * 2 * NH];  // x1+x2+x3 accumulator
__device__ int   g_cnt[4];               // [0]=E stage1, [1]=E after pool1, [2]=after pool2

// ---------------- f32x2 packed helpers ----------------
__device__ __forceinline__ unsigned long long splat2(float x) {
    unsigned long long d;
    asm("mov.b64 %0, {%1, %1};" : "=l"(d) : "r"(__float_as_uint(x)));
    return d;
}
__device__ __forceinline__ void fma2(unsigned long long& acc,
                                     unsigned long long a, unsigned long long b) {
    asm("fma.rn.f32x2 %0, %1, %2, %0;" : "+l"(acc) : "l"(a), "l"(b));
}
__device__ __forceinline__ void unpack2(unsigned long long v, float& lo, float& hi) {
    uint32_t l, h;
    asm("mov.b64 {%0, %1}, %2;" : "=r"(l), "=r"(h) : "l"(v));
    lo = __uint_as_float(l); hi = __uint_as_float(h);
}

// ---------------- kernels ----------------
// one-shot init (runs each replay): zero deg buffers, -1 maps, zero x123, cnts
__global__ void k_init() {
    int i = blockIdx.x * blockDim.x + threadIdx.x;
    if (i < N0MAX) {
        g_deg0[i] = 0; g_deg1[i] = 0; g_deg2[i] = 0;
        g_map0[i] = -1; g_map1[i] = -1; g_map2[i] = -1;
    }
    if (i < BNUM * 2 * NH) g_x123[i] = 0.f;
    if (i == 0) { g_cnt[0] = E0; g_cnt[1] = 0; g_cnt[2] = 0; }
}

__global__ void k_count(const int* __restrict__ dst, const int* __restrict__ cnt,
                        int* __restrict__ deg) {
    int i = blockIdx.x * blockDim.x + threadIdx.x;
    if (i < *cnt) atomicAdd(&deg[dst[i]], 1);
}

// block-level scan via warp shuffles (+ fused degnorm)
__global__ void k_scan1(int N, const int* __restrict__ deg) {
    __shared__ int wsum[32];
    int tid = threadIdx.x;
    int i = blockIdx.x * 1024 + tid;
    int v = (i < N) ? deg[i] : 0;
    if (i < N) {
        float d = (float)v + 1.0f;
        g_dinv[i] = 1.0f / d;
        g_dis[i]  = rsqrtf(d);
    }
    int lane = tid & 31, wid = tid >> 5;
    int incl = v;
    #pragma unroll
    for (int off = 1; off < 32; off <<= 1) {
        int t = __shfl_up_sync(0xffffffffu, incl, off);
        if (lane >= off) incl += t;
    }
    if (lane == 31) wsum[wid] = incl;
    __syncthreads();
    if (wid == 0) {
        int w = wsum[lane];
        #pragma unroll
        for (int off = 1; off < 32; off <<= 1) {
            int t = __shfl_up_sync(0xffffffffu, w, off);
            if (lane >= off) w += t;
        }
        wsum[lane] = w;           // inclusive scan of warp sums
    }
    __syncthreads();
    int wpre = (wid > 0) ? wsum[wid - 1] : 0;
    if (i < N) g_exsc[i] = wpre + incl - v;
    if (tid == 1023) g_bsum[blockIdx.x] = wsum[31];
}

// scan finalize: each block prefixes bsums itself
__global__ void k_scan3(int N, const int* __restrict__ cnt) {
    __shared__ int pref;
    if (threadIdx.x == 0) {
        int s = 0, hb = blockIdx.x >> 2;   // 256*4 = 1024 idx per bsum entry
        for (int j = 0; j < hb; j++) s += g_bsum[j];
        pref = s;
    }
    __syncthreads();
    int i = blockIdx.x * blockDim.x + threadIdx.x;
    if (i < N) {
        int r = g_exsc[i] + pref;
        g_rowptr[i] = r;
        g_cursor[i] = r;
    }
    if (i == 0) g_rowptr[N] = *cnt;
}

__global__ void k_csr(const int* __restrict__ src, const int* __restrict__ dst,
                      const int* __restrict__ cnt) {
    int i = blockIdx.x * blockDim.x + threadIdx.x;
    if (i < *cnt) {
        int d = dst[i];
        int p = atomicAdd(&g_cursor[d], 1);
        g_csr[p] = src[i];
    }
}

// h = X @ W   (X: [N,F] row-major, W: [F,128] row-major) -> g_h
// BM=128, BN=128, BK=16, 256 threads, 8x8 tile, double-buffered, f32x2 packed FMA
__global__ __launch_bounds__(256, 2)
void k_gemm(const float* __restrict__ X, const float* __restrict__ W,
            int N, int F) {
    __shared__ float As[2][16 * 128];   // transposed: As[b][kk][row]
    __shared__ float Bs[2][16 * 128];   // Bs[b][kk][col]
    const int tid = threadIdx.x;
    const int tx = tid & 15, ty = tid >> 4;
    const int rowBase = blockIdx.x * 128;

    const int ar  = tid >> 1;
    const int ac0 = (tid & 1) * 2;
    const int br0 = tid >> 4;
    const int bc0 = (2 * tid) & 31;

    unsigned long long acc2[4][8];
    #pragma unroll
    for (int rp = 0; rp < 4; rp++)
        #pragma unroll
        for (int c = 0; c < 8; c++) acc2[rp][c] = 0ull;

    float4 va0, va1, vb0, vb1;

#define LDT(kt) do {                                                            \
    int grow = rowBase + ar;                                                    \
    if (grow < N) {                                                             \
        va0 = *(const float4*)&X[(size_t)grow * F + (kt) + ac0 * 4];            \
        va1 = *(const float4*)&X[(size_t)grow * F + (kt) + ac0 * 4 + 4];        \
    } else {                                                                    \
        va0 = make_float4(0.f, 0.f, 0.f, 0.f);                                  \
        va1 = make_float4(0.f, 0.f, 0.f, 0.f);                                  \
    }                                                                           \
    vb0 = *(const float4*)&W[(size_t)((kt) + br0) * 128 + bc0 * 4];             \
    vb1 = *(const float4*)&W[(size_t)((kt) + br0) * 128 + bc0 * 4 + 4];         \
} while (0)

#define STT(b) do {                                                             \
    As[b][(ac0 * 4 + 0) * 128 + ar] = va0.x;                                    \
    As[b][(ac0 * 4 + 1) * 128 + ar] = va0.y;                                    \
    As[b][(ac0 * 4 + 2) * 128 + ar] = va0.z;                                    \
    As[b][(ac0 * 4 + 3) * 128 + ar] = va0.w;                                    \
    As[b][(ac0 * 4 + 4) * 128 + ar] = va1.x;                                    \
    As[b][(ac0 * 4 + 5) * 128 + ar] = va1.y;                                    \
    As[b][(ac0 * 4 + 6) * 128 + ar] = va1.z;                                    \
    As[b][(ac0 * 4 + 7) * 128 + ar] = va1.w;                                    \
    *(float4*)&Bs[b][br0 * 128 + bc0 * 4]     = vb0;                            \
    *(float4*)&Bs[b][br0 * 128 + bc0 * 4 + 4] = vb1;                            \
} while (0)

    const int T = F >> 4;
    LDT(0);
    STT(0);
    __syncthreads();

    for (int t = 0; t < T; t++) {
        const int cur = t & 1;
        if (t + 1 < T) LDT((t + 1) * 16);
        #pragma unroll
        for (int kk = 0; kk < 16; kk++) {
            ulonglong2 a01 = *(const ulonglong2*)&As[cur][kk * 128 + ty * 8];
            ulonglong2 a23 = *(const ulonglong2*)&As[cur][kk * 128 + ty * 8 + 4];
            float4 b0 = *(const float4*)&Bs[cur][kk * 128 + tx * 8];
            float4 b1 = *(const float4*)&Bs[cur][kk * 128 + tx * 8 + 4];
            unsigned long long ap[4] = {a01.x, a01.y, a23.x, a23.y};
            unsigned long long bp[8];
            bp[0] = splat2(b0.x); bp[1] = splat2(b0.y);
            bp[2] = splat2(b0.z); bp[3] = splat2(b0.w);
            bp[4] = splat2(b1.x); bp[5] = splat2(b1.y);
            bp[6] = splat2(b1.z); bp[7] = splat2(b1.w);
            #pragma unroll
            for (int rp = 0; rp < 4; rp++)
                #pragma unroll
                for (int c = 0; c < 8; c++)
                    fma2(acc2[rp][c], ap[rp], bp[c]);
        }
        if (t + 1 < T) STT((t + 1) & 1);
        __syncthreads();
    }
#undef LDT
#undef STT

    #pragma unroll
    for (int rp = 0; rp < 4; rp++) {
        float lo[8], hi[8];
        #pragma unroll
        for (int c = 0; c < 8; c++) unpack2(acc2[rp][c], lo[c], hi[c]);
        int gr0 = rowBase + ty * 8 + rp * 2;
        if (gr0 < N) {
            *(float4*)&g_h[(size_t)gr0 * NH + tx * 8] =
                make_float4(lo[0], lo[1], lo[2], lo[3]);
            *(float4*)&g_h[(size_t)gr0 * NH + tx * 8 + 4] =
                make_float4(lo[4], lo[5], lo[6], lo[7]);
        }
        if (gr0 + 1 < N) {
            *(float4*)&g_h[(size_t)(gr0 + 1) * NH + tx * 8] =
                make_float4(hi[0], hi[1], hi[2], hi[3]);
            *(float4*)&g_h[(size_t)(gr0 + 1) * NH + tx * 8 + 4] =
                make_float4(hi[4], hi[5], hi[6], hi[7]);
        }
    }
}

// warp per node: x' = relu(sum_in h[src]*dis[src]*dis[n] + h[n]/deg + b); also h_s = x' . Ws
// 4-deep edge MLP per iteration
__global__ void k_agg(const float* __restrict__ b, const float* __restrict__ Ws, int N) {
    int gid = blockIdx.x * blockDim.x + threadIdx.x;
    int w = gid >> 5, lane = gid & 31;
    if (w >= N) return;
    int beg = g_rowptr[w], end = g_rowptr[w + 1];
    float dn = g_dis[w];
    float4 acc = make_float4(0.f, 0.f, 0.f, 0.f);
    int e = beg;
    for (; e + 4 <= end; e += 4) {
        int s0 = g_csr[e], s1 = g_csr[e + 1], s2 = g_csr[e + 2], s3 = g_csr[e + 3];
        float nm0 = g_dis[s0] * dn, nm1 = g_dis[s1] * dn;
        float nm2 = g_dis[s2] * dn, nm3 = g_dis[s3] * dn;
        float4 h0 = *(const float4*)&g_h[s0 * NH + lane * 4];
        float4 h1 = *(const float4*)&g_h[s1 * NH + lane * 4];
        float4 h2 = *(const float4*)&g_h[s2 * NH + lane * 4];
        float4 h3 = *(const float4*)&g_h[s3 * NH + lane * 4];
        acc.x += h0.x * nm0 + h1.x * nm1 + h2.x * nm2 + h3.x * nm3;
        acc.y += h0.y * nm0 + h1.y * nm1 + h2.y * nm2 + h3.y * nm3;
        acc.z += h0.z * nm0 + h1.z * nm1 + h2.z * nm2 + h3.z * nm3;
        acc.w += h0.w * nm0 + h1.w * nm1 + h2.w * nm2 + h3.w * nm3;
    }
    for (; e < end; e++) {
        int s = g_csr[e];
        float nm = g_dis[s] * dn;
        float4 hv = *(const float4*)&g_h[s * NH + lane * 4];
        acc.x += hv.x * nm; acc.y += hv.y * nm;
        acc.z += hv.z * nm; acc.w += hv.w * nm;
    }
    float di = g_dinv[w];
    float4 hw = *(const float4*)&g_h[w * NH + lane * 4];
    float4 bb = *(const float4*)&b[lane * 4];
    float4 o;
    o.x = fmaxf(acc.x + hw.x * di + bb.x, 0.f);
    o.y = fmaxf(acc.y + hw.y * di + bb.y, 0.f);
    o.z = fmaxf(acc.z + hw.z * di + bb.z, 0.f);
    o.w = fmaxf(acc.w + hw.w * di + bb.w, 0.f);
    *(float4*)&g_xa[w * NH + lane * 4] = o;
    float4 wv = *(const float4*)&Ws[lane * 4];
    float d = o.x * wv.x + o.y * wv.y + o.z * wv.z + o.w * wv.w;
    #pragma unroll
    for (int off = 16; off; off >>= 1) d += __shfl_xor_sync(0xffffffffu, d, off);
    if (lane == 0) g_hs[w] = d;
}

// block per graph: fused score-aggregation, bitonic sort, vectorized pool + readout
__launch_bounds__(1024)
__global__ void k_topk(int n, int k, int* __restrict__ map,
                       const float* __restrict__ bs) {
    __shared__ float sbuf[6144];         // [0:2048)=ss, [2048:4096)=si, [4096:6144)=st
    float* ss = sbuf;
    int*   si = (int*)(sbuf + 2048);
    float* st = sbuf + 4096;
    int g = blockIdx.x, tid = threadIdx.x;
    float bias = bs[0];
    // fused sagg: score for this graph's nodes
    for (int j = tid; j < 2048; j += 1024) {
        float sc = -3.402823466e38f;
        if (j < n) {
            int i = g * n + j;
            int beg = g_rowptr[i], end = g_rowptr[i + 1];
            float s = 0.f;
            for (int e = beg; e < end; e++) {
                int u = g_csr[e];
                s += g_hs[u] * g_dis[u];
            }
            sc = s * g_dis[i] + g_hs[i] * g_dinv[i] + bias;
        }
        ss[j] = sc; si[j] = j;
    }
    __syncthreads();
    for (int kk = 2; kk <= 2048; kk <<= 1) {
        for (int jj = kk >> 1; jj > 0; jj >>= 1) {
            for (int i = tid; i < 2048; i += 1024) {
                int l = i ^ jj;
                if (l > i) {
                    float si_ = ss[i], sl_ = ss[l];
                    int ii_ = si[i], il_ = si[l];
                    bool before = (si_ > sl_) || (si_ == sl_ && ii_ < il_);
                    bool asc = ((i & kk) == 0);
                    if (asc != before) {
                        ss[i] = sl_; ss[l] = si_;
                        si[i] = il_; si[l] = ii_;
                    }
                }
            }
            __syncthreads();
        }
    }
    for (int j = tid; j < k; j += 1024) {
        int p = g * n + si[j];
        map[p] = g * k + j;
        st[j] = tanhf(ss[j]);
    }
    __syncthreads();
    // vectorized pool + readout: 16 node-groups x 64 float2-lanes (128 features)
    // k is a multiple of 32 for all stages (1600/1280/1024)
    int f0 = (tid & 63) * 2, grp = tid >> 6;
    float2 mx = make_float2(-3.402823466e38f, -3.402823466e38f);
    float2 sm = make_float2(0.f, 0.f);
    for (int i = grp; i < k; i += 16) {
        int p = g * n + si[i];
        float t = st[i];
        float2 v = *(const float2*)&g_xa[p * NH + f0];
        v.x *= t; v.y *= t;
        *(float2*)&g_xb[(size_t)(g * k + i) * NH + f0] = v;
        mx.x = fmaxf(mx.x, v.x); mx.y = fmaxf(mx.y, v.y);
        sm.x += v.x; sm.y += v.y;
    }
    __syncthreads();                     // everyone done reading si/ss regions
    // partials: max -> sbuf[0:2048), sum -> sbuf[2048:4096)   (st region preserved)
    *(float2*)&sbuf[grp * 128 + f0] = mx;
    *(float2*)&sbuf[2048 + grp * 128 + f0] = sm;
    __syncthreads();
    if (tid < 128) {
        float m = -3.402823466e38f, s2 = 0.f;
        #pragma unroll
        for (int g2 = 0; g2 < 16; g2++) {
            m = fmaxf(m, sbuf[g2 * 128 + tid]);
            s2 += sbuf[2048 + g2 * 128 + tid];
        }
        g_x123[g * (2 * NH) + tid]      += m;
        g_x123[g * (2 * NH) + NH + tid] += s2 / (float)k;
    }
}

// filter + fused degree count; warp-aggregated counter atomic
__global__ void k_filtcnt(const int* __restrict__ src, const int* __restrict__ dst,
                          const int* __restrict__ cnt, const int* __restrict__ map,
                          int* __restrict__ nsrc, int* __restrict__ ndst,
                          int* __restrict__ ncnt, int* __restrict__ deg) {
    int i = blockIdx.x * blockDim.x + threadIdx.x;
    int lane = threadIdx.x & 31;
    int a = -1, b = -1;
    bool valid = false;
    if (i < *cnt) {
        a = map[src[i]];
        b = map[dst[i]];
        valid = (a >= 0 && b >= 0);
    }
    unsigned m = __ballot_sync(0xffffffffu, valid);
    if (m == 0) return;
    int leader = __ffs(m) - 1;
    int base = 0;
    if (lane == leader) base = atomicAdd(ncnt, __popc(m));
    base = __shfl_sync(0xffffffffu, base, leader);
    if (valid) {
        int pos = base + __popc(m & ((1u << lane) - 1u));
        nsrc[pos] = a;
        ndst[pos] = b;
        atomicAdd(&deg[b], 1);
    }
}

__global__ void k_final(const float* __restrict__ Wl, const float* __restrict__ bl,
                        float* __restrict__ out) {
    int g = blockIdx.x, o = threadIdx.x;
    float acc = bl[o];
    #pragma unroll 4
    for (int f = 0; f < 2 * NH; f++)
        acc = fmaf(g_x123[g * (2 * NH) + f], Wl[f * NH + o], acc);
    out[g * NH + o] = fmaxf(acc, 0.f);
}

// ---------------- host driver ----------------
extern "C" void kernel_launch(void* const* d_in, const int* in_sizes, int n_in,
                              void* d_out, int out_size) {
    static cudaStream_t s2 = nullptr;
    static cudaEvent_t evF = nullptr, evJ = nullptr;
    if (!s2) {
        cudaStreamCreateWithFlags(&s2, cudaStreamNonBlocking);
        cudaEventCreateWithFlags(&evF, cudaEventDisableTiming);
        cudaEventCreateWithFlags(&evJ, cudaEventDisableTiming);
    }

    const float* x   = (const float*)d_in[0];
    const float* W1  = (const float*)d_in[1];
    const float* b1  = (const float*)d_in[2];
    const float* Ws1 = (const float*)d_in[3];
    const float* bs1 = (const float*)d_in[4];
    const float* W2  = (const float*)d_in[5];
    const float* b2  = (const float*)d_in[6];
    const float* Ws2 = (const float*)d_in[7];
    const float* bs2 = (const float*)d_in[8];
    const float* W3  = (const float*)d_in[9];
    const float* b3  = (const float*)d_in[10];
    const float* Ws3 = (const float*)d_in[11];
    const float* bs3 = (const float*)d_in[12];
    const float* Wl  = (const float*)d_in[13];
    const float* bl  = (const float*)d_in[14];
    const int*   ei  = (const int*)d_in[15];
    float* out = (float*)d_out;

    int *p_es0, *p_ed0, *p_es1, *p_ed1, *p_cnt;
    int *p_deg0, *p_deg1, *p_deg2, *p_map0, *p_map1, *p_map2;
    float* p_xb;
    cudaGetSymbolAddress((void**)&p_es0, g_esrc0);
    cudaGetSymbolAddress((void**)&p_ed0, g_edst0);
    cudaGetSymbolAddress((void**)&p_es1, g_esrc1);
    cudaGetSymbolAddress((void**)&p_ed1, g_edst1);
    cudaGetSymbolAddress((void**)&p_cnt, g_cnt);
    cudaGetSymbolAddress((void**)&p_deg0, g_deg0);
    cudaGetSymbolAddress((void**)&p_deg1, g_deg1);
    cudaGetSymbolAddress((void**)&p_deg2, g_deg2);
    cudaGetSymbolAddress((void**)&p_map0, g_map0);
    cudaGetSymbolAddress((void**)&p_map1, g_map1);
    cudaGetSymbolAddress((void**)&p_map2, g_map2);
    cudaGetSymbolAddress((void**)&p_xb,  g_xb);

    const int EB = (E0 + 255) / 256;

    // ================= stage 1: N=100000, F=256, n=2000, k=1600 =================
    {
        const int Nin = 100000, n = 2000, kk = 1600;
        int nb = (Nin + 1023) / 1024;
        // fork side stream FIRST: gemm1 is independent of init/count/scan chain
        cudaEventRecord(evF, 0);
        cudaStreamWaitEvent(s2, evF, 0);
        k_gemm<<<(Nin + 127) / 128, 256, 0, s2>>>(x, W1, Nin, FIN);
        cudaEventRecord(evJ, s2);
        k_init<<<(N0MAX + 255) / 256, 256>>>();
        k_count<<<EB, 256>>>(ei + E0, p_cnt + 0, p_deg0);
        k_scan1<<<nb, 1024>>>(Nin, p_deg0);
        k_scan3<<<(Nin + 255) / 256, 256>>>(Nin, p_cnt + 0);
        k_csr<<<EB, 256>>>(ei, ei + E0, p_cnt + 0);
        cudaStreamWaitEvent(0, evJ, 0);
        k_agg<<<(Nin * 32 + 255) / 256, 256>>>(b1, Ws1, Nin);
        k_topk<<<BNUM, 1024>>>(n, kk, p_map0, bs1);
    }

    // ================= stage 2: N=80000, F=128, n=1600, k=1280 =================
    {
        const int Nin = 80000, n = 1600, kk = 1280;
        int nb = (Nin + 1023) / 1024;
        cudaEventRecord(evF, 0);                    // after topk1: g_xb ready
        cudaStreamWaitEvent(s2, evF, 0);
        k_gemm<<<(Nin + 127) / 128, 256, 0, s2>>>(p_xb, W2, Nin, NH);
        cudaEventRecord(evJ, s2);
        k_filtcnt<<<EB, 256>>>(ei, ei + E0, p_cnt + 0, p_map0,
                               p_es0, p_ed0, p_cnt + 1, p_deg1);
        k_scan1<<<nb, 1024>>>(Nin, p_deg1);
        k_scan3<<<(Nin + 255) / 256, 256>>>(Nin, p_cnt + 1);
        k_csr<<<EB, 256>>>(p_es0, p_ed0, p_cnt + 1);
        cudaStreamWaitEvent(0, evJ, 0);
        k_agg<<<(Nin * 32 + 255) / 256, 256>>>(b2, Ws2, Nin);
        k_topk<<<BNUM, 1024>>>(n, kk, p_map1, bs2);
    }

    // ================= stage 3: N=64000, F=128, n=1280, k=1024 =================
    {
        const int Nin = 64000, n = 1280, kk = 1024;
        int nb = (Nin + 1023) / 1024;
        cudaEventRecord(evF, 0);
        cudaStreamWaitEvent(s2, evF, 0);
        k_gemm<<<(Nin + 127) / 128, 256, 0, s2>>>(p_xb, W3, Nin, NH);
        cudaEventRecord(evJ, s2);
        k_filtcnt<<<EB, 256>>>(p_es0, p_ed0, p_cnt + 1, p_map1,
                               p_es1, p_ed1, p_cnt + 2, p_deg2);
        k_scan1<<<nb, 1024>>>(Nin, p_deg2);
        k_scan3<<<(Nin + 255) / 256, 256>>>(Nin, p_cnt + 2);
        k_csr<<<EB, 256>>>(p_es1, p_ed1, p_cnt + 2);
        cudaStreamWaitEvent(0, evJ, 0);
        k_agg<<<(Nin * 32 + 255) / 256, 256>>>(b3, Ws3, Nin);
        k_topk<<<BNUM, 1024>>>(n, kk, p_map2, bs3);
    }

    k_final<<<BNUM, NH>>>(Wl, bl, out);
}

// round 13
// speedup vs baseline: 1.2593x; 1.0988x over previous
#include <cuda_runtime.h>
#include <math.h>
#include <stdint.h>

#define BNUM  50
#define E0    600000
#define FIN   256
#define NH    128
#define N0MAX 100000
#define N1MAX 80000

// ---------------- scratch (device globals; no allocs allowed) ----------------
__device__ float g_h[N0MAX * NH];        // GEMM output h = x @ W
__device__ float g_xa[N0MAX * NH];       // conv output x' (post-relu)
__device__ float g_hs[N0MAX];            // score projection h_s = x' . Ws
__device__ int   g_deg0[N0MAX], g_deg1[N0MAX], g_deg2[N0MAX];
__device__ int   g_map0[N0MAX], g_map1[N0MAX], g_map2[N0MAX];
__device__ float g_dis[N0MAX];           // rsqrt(deg+1)
__device__ float g_dinv[N0MAX];          // 1/(deg+1)
__device__ int   g_rowptr[N0MAX + 1];
__device__ int   g_cursor[N0MAX];
__device__ int   g_exsc[N0MAX];
__device__ int   g_bsum[128];
__device__ int   g_csr[E0];              // src ids bucketed by dst
__device__ int   g_esrc0[E0], g_edst0[E0];
__device__ int   g_esrc1[E0], g_edst1[E0];
__device__ int   g_pm[N1MAX];            // perm: new id -> old global node id
__device__ float g_pts[N1MAX];           // tanh(score) per new id
__device__ float g_x123[BNUM * 2 * NH];  // x1+x2+x3 accumulator
__device__ int   g_cnt[4];               // [0]=E stage1, [1]=E after pool1, [2]=after pool2

// ---------------- f32x2 packed helpers ----------------
__device__ __forceinline__ unsigned long long splat2(float x) {
    unsigned long long d;
    asm("mov.b64 %0, {%1, %1};" : "=l"(d) : "r"(__float_as_uint(x)));
    return d;
}
__device__ __forceinline__ void fma2(unsigned long long& acc,
                                     unsigned long long a, unsigned long long b) {
    asm("fma.rn.f32x2 %0, %1, %2, %0;" : "+l"(acc) : "l"(a), "l"(b));
}
__device__ __forceinline__ void unpack2(unsigned long long v, float& lo, float& hi) {
    uint32_t l, h;
    asm("mov.b64 {%0, %1}, %2;" : "=r"(l), "=r"(h) : "l"(v));
    lo = __uint_as_float(l); hi = __uint_as_float(h);
}

// ---------------- kernels ----------------
// one-shot init (runs each replay): zero deg buffers, -1 maps, zero x123, cnts
__global__ void k_init() {
    int i = blockIdx.x * blockDim.x + threadIdx.x;
    if (i < N0MAX) {
        g_deg0[i] = 0; g_deg1[i] = 0; g_deg2[i] = 0;
        g_map0[i] = -1; g_map1[i] = -1; g_map2[i] = -1;
    }
    if (i < BNUM * 2 * NH) g_x123[i] = 0.f;
    if (i == 0) { g_cnt[0] = E0; g_cnt[1] = 0; g_cnt[2] = 0; }
}

__global__ void k_count(const int* __restrict__ dst, const int* __restrict__ cnt,
                        int* __restrict__ deg) {
    int i = blockIdx.x * blockDim.x + threadIdx.x;
    if (i < *cnt) atomicAdd(&deg[dst[i]], 1);
}

// block-level scan via warp shuffles (+ fused degnorm)
__global__ void k_scan1(int N, const int* __restrict__ deg) {
    __shared__ int wsum[32];
    int tid = threadIdx.x;
    int i = blockIdx.x * 1024 + tid;
    int v = (i < N) ? deg[i] : 0;
    if (i < N) {
        float d = (float)v + 1.0f;
        g_dinv[i] = 1.0f / d;
        g_dis[i]  = rsqrtf(d);
    }
    int lane = tid & 31, wid = tid >> 5;
    int incl = v;
    #pragma unroll
    for (int off = 1; off < 32; off <<= 1) {
        int t = __shfl_up_sync(0xffffffffu, incl, off);
        if (lane >= off) incl += t;
    }
    if (lane == 31) wsum[wid] = incl;
    __syncthreads();
    if (wid == 0) {
        int w = wsum[lane];
        #pragma unroll
        for (int off = 1; off < 32; off <<= 1) {
            int t = __shfl_up_sync(0xffffffffu, w, off);
            if (lane >= off) w += t;
        }
        wsum[lane] = w;           // inclusive scan of warp sums
    }
    __syncthreads();
    int wpre = (wid > 0) ? wsum[wid - 1] : 0;
    if (i < N) g_exsc[i] = wpre + incl - v;
    if (tid == 1023) g_bsum[blockIdx.x] = wsum[31];
}

// scan finalize: each block prefixes bsums itself
__global__ void k_scan3(int N, const int* __restrict__ cnt) {
    __shared__ int pref;
    if (threadIdx.x == 0) {
        int s = 0, hb = blockIdx.x >> 2;   // 256*4 = 1024 idx per bsum entry
        for (int j = 0; j < hb; j++) s += g_bsum[j];
        pref = s;
    }
    __syncthreads();
    int i = blockIdx.x * blockDim.x + threadIdx.x;
    if (i < N) {
        int r = g_exsc[i] + pref;
        g_rowptr[i] = r;
        g_cursor[i] = r;
    }
    if (i == 0) g_rowptr[N] = *cnt;
}

__global__ void k_csr(const int* __restrict__ src, const int* __restrict__ dst,
                      const int* __restrict__ cnt) {
    int i = blockIdx.x * blockDim.x + threadIdx.x;
    if (i < *cnt) {
        int d = dst[i];
        int p = atomicAdd(&g_cursor[d], 1);
        g_csr[p] = src[i];
    }
}

// h = A @ W  -> g_h.  A row r = X[perm[r]] * pscale[r]  (or X[r] when perm==null).
// BM=128, BN=128, BK=16, 256 threads, 8x8 tile, double-buffered, f32x2 packed FMA
__global__ __launch_bounds__(256, 2)
void k_gemm(const float* __restrict__ X, const float* __restrict__ W,
            int N, int F, const int* __restrict__ perm,
            const float* __restrict__ pscale) {
    __shared__ float As[2][16 * 128];   // transposed: As[b][kk][row]
    __shared__ float Bs[2][16 * 128];   // Bs[b][kk][col]
    const int tid = threadIdx.x;
    const int tx = tid & 15, ty = tid >> 4;
    const int rowBase = blockIdx.x * 128;

    const int ar  = tid >> 1;
    const int ac0 = (tid & 1) * 2;
    const int br0 = tid >> 4;
    const int bc0 = (2 * tid) & 31;

    // hoist per-row gather pointer + scale (invariant across K loop)
    const int grow = rowBase + ar;
    const bool rowok = grow < N;
    const float* Xr = X;
    float ascl = 1.f;
    if (rowok) {
        int r = grow;
        if (perm) { r = perm[grow]; ascl = pscale[grow]; }
        Xr = X + (size_t)r * F;
    }

    unsigned long long acc2[4][8];
    #pragma unroll
    for (int rp = 0; rp < 4; rp++)
        #pragma unroll
        for (int c = 0; c < 8; c++) acc2[rp][c] = 0ull;

    float4 va0, va1, vb0, vb1;

#define LDT(kt) do {                                                            \
    if (rowok) {                                                                \
        va0 = *(const float4*)&Xr[(kt) + ac0 * 4];                              \
        va1 = *(const float4*)&Xr[(kt) + ac0 * 4 + 4];                          \
        va0.x *= ascl; va0.y *= ascl; va0.z *= ascl; va0.w *= ascl;             \
        va1.x *= ascl; va1.y *= ascl; va1.z *= ascl; va1.w *= ascl;             \
    } else {                                                                    \
        va0 = make_float4(0.f, 0.f, 0.f, 0.f);                                  \
        va1 = make_float4(0.f, 0.f, 0.f, 0.f);                                  \
    }                                                                           \
    vb0 = *(const float4*)&W[(size_t)((kt) + br0) * 128 + bc0 * 4];             \
    vb1 = *(const float4*)&W[(size_t)((kt) + br0) * 128 + bc0 * 4 + 4];         \
} while (0)

#define STT(b) do {                                                             \
    As[b][(ac0 * 4 + 0) * 128 + ar] = va0.x;                                    \
    As[b][(ac0 * 4 + 1) * 128 + ar] = va0.y;                                    \
    As[b][(ac0 * 4 + 2) * 128 + ar] = va0.z;                                    \
    As[b][(ac0 * 4 + 3) * 128 + ar] = va0.w;                                    \
    As[b][(ac0 * 4 + 4) * 128 + ar] = va1.x;                                    \
    As[b][(ac0 * 4 + 5) * 128 + ar] = va1.y;                                    \
    As[b][(ac0 * 4 + 6) * 128 + ar] = va1.z;                                    \
    As[b][(ac0 * 4 + 7) * 128 + ar] = va1.w;                                    \
    *(float4*)&Bs[b][br0 * 128 + bc0 * 4]     = vb0;                            \
    *(float4*)&Bs[b][br0 * 128 + bc0 * 4 + 4] = vb1;                            \
} while (0)

    const int T = F >> 4;
    LDT(0);
    STT(0);
    __syncthreads();

    for (int t = 0; t < T; t++) {
        const int cur = t & 1;
        if (t + 1 < T) LDT((t + 1) * 16);
        #pragma unroll
        for (int kk = 0; kk < 16; kk++) {
            ulonglong2 a01 = *(const ulonglong2*)&As[cur][kk * 128 + ty * 8];
            ulonglong2 a23 = *(const ulonglong2*)&As[cur][kk * 128 + ty * 8 + 4];
            float4 b0 = *(const float4*)&Bs[cur][kk * 128 + tx * 8];
            float4 b1 = *(const float4*)&Bs[cur][kk * 128 + tx * 8 + 4];
            unsigned long long ap[4] = {a01.x, a01.y, a23.x, a23.y};
            unsigned long long bp[8];
            bp[0] = splat2(b0.x); bp[1] = splat2(b0.y);
            bp[2] = splat2(b0.z); bp[3] = splat2(b0.w);
            bp[4] = splat2(b1.x); bp[5] = splat2(b1.y);
            bp[6] = splat2(b1.z); bp[7] = splat2(b1.w);
            #pragma unroll
            for (int rp = 0; rp < 4; rp++)
                #pragma unroll
                for (int c = 0; c < 8; c++)
                    fma2(acc2[rp][c], ap[rp], bp[c]);
        }
        if (t + 1 < T) STT((t + 1) & 1);
        __syncthreads();
    }
#undef LDT
#undef STT

    #pragma unroll
    for (int rp = 0; rp < 4; rp++) {
        float lo[8], hi[8];
        #pragma unroll
        for (int c = 0; c < 8; c++) unpack2(acc2[rp][c], lo[c], hi[c]);
        int gr0 = rowBase + ty * 8 + rp * 2;
        if (gr0 < N) {
            *(float4*)&g_h[(size_t)gr0 * NH + tx * 8] =
                make_float4(lo[0], lo[1], lo[2], lo[3]);
            *(float4*)&g_h[(size_t)gr0 * NH + tx * 8 + 4] =
                make_float4(lo[4], lo[5], lo[6], lo[7]);
        }
        if (gr0 + 1 < N) {
            *(float4*)&g_h[(size_t)(gr0 + 1) * NH + tx * 8] =
                make_float4(hi[0], hi[1], hi[2], hi[3]);
            *(float4*)&g_h[(size_t)(gr0 + 1) * NH + tx * 8 + 4] =
                make_float4(hi[4], hi[5], hi[6], hi[7]);
        }
    }
}

// warp per node: x' = relu(sum_in h[src]*dis[src]*dis[n] + h[n]/deg + b); also h_s = x' . Ws
__global__ void k_agg(const float* __restrict__ b, const float* __restrict__ Ws, int N) {
    int gid = blockIdx.x * blockDim.x + threadIdx.x;
    int w = gid >> 5, lane = gid & 31;
    if (w >= N) return;
    int beg = g_rowptr[w], end = g_rowptr[w + 1];
    float dn = g_dis[w];
    float4 acc = make_float4(0.f, 0.f, 0.f, 0.f);
    int e = beg;
    for (; e + 4 <= end; e += 4) {
        int s0 = g_csr[e], s1 = g_csr[e + 1], s2 = g_csr[e + 2], s3 = g_csr[e + 3];
        float nm0 = g_dis[s0] * dn, nm1 = g_dis[s1] * dn;
        float nm2 = g_dis[s2] * dn, nm3 = g_dis[s3] * dn;
        float4 h0 = *(const float4*)&g_h[s0 * NH + lane * 4];
        float4 h1 = *(const float4*)&g_h[s1 * NH + lane * 4];
        float4 h2 = *(const float4*)&g_h[s2 * NH + lane * 4];
        float4 h3 = *(const float4*)&g_h[s3 * NH + lane * 4];
        acc.x += h0.x * nm0 + h1.x * nm1 + h2.x * nm2 + h3.x * nm3;
        acc.y += h0.y * nm0 + h1.y * nm1 + h2.y * nm2 + h3.y * nm3;
        acc.z += h0.z * nm0 + h1.z * nm1 + h2.z * nm2 + h3.z * nm3;
        acc.w += h0.w * nm0 + h1.w * nm1 + h2.w * nm2 + h3.w * nm3;
    }
    for (; e < end; e++) {
        int s = g_csr[e];
        float nm = g_dis[s] * dn;
        float4 hv = *(const float4*)&g_h[s * NH + lane * 4];
        acc.x += hv.x * nm; acc.y += hv.y * nm;
        acc.z += hv.z * nm; acc.w += hv.w * nm;
    }
    float di = g_dinv[w];
    float4 hw = *(const float4*)&g_h[w * NH + lane * 4];
    float4 bb = *(const float4*)&b[lane * 4];
    float4 o;
    o.x = fmaxf(acc.x + hw.x * di + bb.x, 0.f);
    o.y = fmaxf(acc.y + hw.y * di + bb.y, 0.f);
    o.z = fmaxf(acc.z + hw.z * di + bb.z, 0.f);
    o.w = fmaxf(acc.w + hw.w * di + bb.w, 0.f);
    *(float4*)&g_xa[w * NH + lane * 4] = o;
    float4 wv = *(const float4*)&Ws[lane * 4];
    float d = o.x * wv.x + o.y * wv.y + o.z * wv.z + o.w * wv.w;
    #pragma unroll
    for (int off = 16; off; off >>= 1) d += __shfl_xor_sync(0xffffffffu, d, off);
    if (lane == 0) g_hs[w] = d;
}

// block per graph: fused score-agg, bitonic sort, readout (no pooled-feature write;
// next-stage GEMM gathers via perm+pts instead)
__launch_bounds__(1024)
__global__ void k_topk(int n, int k, int* __restrict__ map,
                       const float* __restrict__ bs,
                       int* __restrict__ perm, float* __restrict__ pts) {
    __shared__ float sbuf[6144];         // [0:2048)=ss, [2048:4096)=si, [4096:6144)=st
    float* ss = sbuf;
    int*   si = (int*)(sbuf + 2048);
    float* st = sbuf + 4096;
    int g = blockIdx.x, tid = threadIdx.x;
    float bias = bs[0];
    // fused sagg: score for this graph's nodes
    for (int j = tid; j < 2048; j += 1024) {
        float sc = -3.402823466e38f;
        if (j < n) {
            int i = g * n + j;
            int beg = g_rowptr[i], end = g_rowptr[i + 1];
            float s = 0.f;
            for (int e = beg; e < end; e++) {
                int u = g_csr[e];
                s += g_hs[u] * g_dis[u];
            }
            sc = s * g_dis[i] + g_hs[i] * g_dinv[i] + bias;
        }
        ss[j] = sc; si[j] = j;
    }
    __syncthreads();
    for (int kk = 2; kk <= 2048; kk <<= 1) {
        for (int jj = kk >> 1; jj > 0; jj >>= 1) {
            for (int i = tid; i < 2048; i += 1024) {
                int l = i ^ jj;
                if (l > i) {
                    float si_ = ss[i], sl_ = ss[l];
                    int ii_ = si[i], il_ = si[l];
                    bool before = (si_ > sl_) || (si_ == sl_ && ii_ < il_);
                    bool asc = ((i & kk) == 0);
                    if (asc != before) {
                        ss[i] = sl_; ss[l] = si_;
                        si[i] = il_; si[l] = ii_;
                    }
                }
            }
            __syncthreads();
        }
    }
    for (int j = tid; j < k; j += 1024) {
        int p = g * n + si[j];
        float t = tanhf(ss[j]);
        map[p] = g * k + j;
        perm[g * k + j] = p;
        pts[g * k + j] = t;
        st[j] = t;
    }
    __syncthreads();
    // readout: gather 16 node-groups x 64 float2-lanes; no g_xb write
    int f0 = (tid & 63) * 2, grp = tid >> 6;
    float2 mx = make_float2(-3.402823466e38f, -3.402823466e38f);
    float2 sm = make_float2(0.f, 0.f);
    for (int i = grp; i < k; i += 16) {
        int p = g * n + si[i];
        float t = st[i];
        float2 v = *(const float2*)&g_xa[p * NH + f0];
        v.x *= t; v.y *= t;
        mx.x = fmaxf(mx.x, v.x); mx.y = fmaxf(mx.y, v.y);
        sm.x += v.x; sm.y += v.y;
    }
    __syncthreads();
    *(float2*)&sbuf[grp * 128 + f0] = mx;
    *(float2*)&sbuf[2048 + grp * 128 + f0] = sm;
    __syncthreads();
    if (tid < 128) {
        float m = -3.402823466e38f, s2 = 0.f;
        #pragma unroll
        for (int g2 = 0; g2 < 16; g2++) {
            m = fmaxf(m, sbuf[g2 * 128 + tid]);
            s2 += sbuf[2048 + g2 * 128 + tid];
        }
        g_x123[g * (2 * NH) + tid]      += m;
        g_x123[g * (2 * NH) + NH + tid] += s2 / (float)k;
    }
}

// filter + fused degree count; warp-aggregated counter atomic
__global__ void k_filtcnt(const int* __restrict__ src, const int* __restrict__ dst,
                          const int* __restrict__ cnt, const int* __restrict__ map,
                          int* __restrict__ nsrc, int* __restrict__ ndst,
                          int* __restrict__ ncnt, int* __restrict__ deg) {
    int i = blockIdx.x * blockDim.x + threadIdx.x;
    int lane = threadIdx.x & 31;
    int a = -1, b = -1;
    bool valid = false;
    if (i < *cnt) {
        a = map[src[i]];
        b = map[dst[i]];
        valid = (a >= 0 && b >= 0);
    }
    unsigned m = __ballot_sync(0xffffffffu, valid);
    if (m == 0) return;
    int leader = __ffs(m) - 1;
    int base = 0;
    if (lane == leader) base = atomicAdd(ncnt, __popc(m));
    base = __shfl_sync(0xffffffffu, base, leader);
    if (valid) {
        int pos = base + __popc(m & ((1u << lane) - 1u));
        nsrc[pos] = a;
        ndst[pos] = b;
        atomicAdd(&deg[b], 1);
    }
}

__global__ void k_final(const float* __restrict__ Wl, const float* __restrict__ bl,
                        float* __restrict__ out) {
    int g = blockIdx.x, o = threadIdx.x;
    float acc = bl[o];
    #pragma unroll 4
    for (int f = 0; f < 2 * NH; f++)
        acc = fmaf(g_x123[g * (2 * NH) + f], Wl[f * NH + o], acc);
    out[g * NH + o] = fmaxf(acc, 0.f);
}

// ---------------- host driver ----------------
extern "C" void kernel_launch(void* const* d_in, const int* in_sizes, int n_in,
                              void* d_out, int out_size) {
    static cudaStream_t s2 = nullptr;
    static cudaEvent_t evF = nullptr, evJ = nullptr;
    if (!s2) {
        cudaStreamCreateWithFlags(&s2, cudaStreamNonBlocking);
        cudaEventCreateWithFlags(&evF, cudaEventDisableTiming);
        cudaEventCreateWithFlags(&evJ, cudaEventDisableTiming);
    }

    const float* x   = (const float*)d_in[0];
    const float* W1  = (const float*)d_in[1];
    const float* b1  = (const float*)d_in[2];
    const float* Ws1 = (const float*)d_in[3];
    const float* bs1 = (const float*)d_in[4];
    const float* W2  = (const float*)d_in[5];
    const float* b2  = (const float*)d_in[6];
    const float* Ws2 = (const float*)d_in[7];
    const float* bs2 = (const float*)d_in[8];
    const float* W3  = (const float*)d_in[9];
    const float* b3  = (const float*)d_in[10];
    const float* Ws3 = (const float*)d_in[11];
    const float* bs3 = (const float*)d_in[12];
    const float* Wl  = (const float*)d_in[13];
    const float* bl  = (const float*)d_in[14];
    const int*   ei  = (const int*)d_in[15];
    float* out = (float*)d_out;

    int *p_es0, *p_ed0, *p_es1, *p_ed1, *p_cnt;
    int *p_deg0, *p_deg1, *p_deg2, *p_map0, *p_map1, *p_map2, *p_pm;
    float *p_xa, *p_pts;
    cudaGetSymbolAddress((void**)&p_es0, g_esrc0);
    cudaGetSymbolAddress((void**)&p_ed0, g_edst0);
    cudaGetSymbolAddress((void**)&p_es1, g_esrc1);
    cudaGetSymbolAddress((void**)&p_ed1, g_edst1);
    cudaGetSymbolAddress((void**)&p_cnt, g_cnt);
    cudaGetSymbolAddress((void**)&p_deg0, g_deg0);
    cudaGetSymbolAddress((void**)&p_deg1, g_deg1);
    cudaGetSymbolAddress((void**)&p_deg2, g_deg2);
    cudaGetSymbolAddress((void**)&p_map0, g_map0);
    cudaGetSymbolAddress((void**)&p_map1, g_map1);
    cudaGetSymbolAddress((void**)&p_map2, g_map2);
    cudaGetSymbolAddress((void**)&p_pm,  g_pm);
    cudaGetSymbolAddress((void**)&p_pts, g_pts);
    cudaGetSymbolAddress((void**)&p_xa,  g_xa);

    const int EB = (E0 + 255) / 256;

    // ================= stage 1: N=100000, F=256, n=2000, k=1600 =================
    {
        const int Nin = 100000, n = 2000, kk = 1600;
        int nb = (Nin + 1023) / 1024;
        // GEMM on main (critical path); CSR chain on side stream
        cudaEventRecord(evF, 0);
        cudaStreamWaitEvent(s2, evF, 0);
        k_gemm<<<(Nin + 127) / 128, 256>>>(x, W1, Nin, FIN, nullptr, nullptr);
        k_init<<<(N0MAX + 255) / 256, 256, 0, s2>>>();
        k_count<<<EB, 256, 0, s2>>>(ei + E0, p_cnt + 0, p_deg0);
        k_scan1<<<nb, 1024, 0, s2>>>(Nin, p_deg0);
        k_scan3<<<(Nin + 255) / 256, 256, 0, s2>>>(Nin, p_cnt + 0);
        k_csr<<<EB, 256, 0, s2>>>(ei, ei + E0, p_cnt + 0);
        cudaEventRecord(evJ, s2);
        cudaStreamWaitEvent(0, evJ, 0);
        k_agg<<<(Nin * 32 + 255) / 256, 256>>>(b1, Ws1, Nin);
        k_topk<<<BNUM, 1024>>>(n, kk, p_map0, bs1, p_pm, p_pts);
    }

    // ================= stage 2: N=80000, F=128, n=1600, k=1280 =================
    {
        const int Nin = 80000, n = 1600, kk = 1280;
        int nb = (Nin + 1023) / 1024;
        cudaEventRecord(evF, 0);                    // after topk1
        cudaStreamWaitEvent(s2, evF, 0);
        // GEMM gathers pooled rows from g_xa via perm/pts (no g_xb materialization)
        k_gemm<<<(Nin + 127) / 128, 256>>>(p_xa, W2, Nin, NH, p_pm, p_pts);
        k_filtcnt<<<EB, 256, 0, s2>>>(ei, ei + E0, p_cnt + 0, p_map0,
                                      p_es0, p_ed0, p_cnt + 1, p_deg1);
        k_scan1<<<nb, 1024, 0, s2>>>(Nin, p_deg1);
        k_scan3<<<(Nin + 255) / 256, 256, 0, s2>>>(Nin, p_cnt + 1);
        k_csr<<<EB, 256, 0, s2>>>(p_es0, p_ed0, p_cnt + 1);
        cudaEventRecord(evJ, s2);
        cudaStreamWaitEvent(0, evJ, 0);
        k_agg<<<(Nin * 32 + 255) / 256, 256>>>(b2, Ws2, Nin);
        k_topk<<<BNUM, 1024>>>(n, kk, p_map1, bs2, p_pm, p_pts);
    }

    // ================= stage 3: N=64000, F=128, n=1280, k=1024 =================
    {
        const int Nin = 64000, n = 1280, kk = 1024;
        int nb = (Nin + 1023) / 1024;
        cudaEventRecord(evF, 0);
        cudaStreamWaitEvent(s2, evF, 0);
        k_gemm<<<(Nin + 127) / 128, 256>>>(p_xa, W3, Nin, NH, p_pm, p_pts);
        k_filtcnt<<<EB, 256, 0, s2>>>(p_es0, p_ed0, p_cnt + 1, p_map1,
                                      p_es1, p_ed1, p_cnt + 2, p_deg2);
        k_scan1<<<nb, 1024, 0, s2>>>(Nin, p_deg2);
        k_scan3<<<(Nin + 255) / 256, 256, 0, s2>>>(Nin, p_cnt + 2);
        k_csr<<<EB, 256, 0, s2>>>(p_es1, p_ed1, p_cnt + 2);
        cudaEventRecord(evJ, s2);
        cudaStreamWaitEvent(0, evJ, 0);
        k_agg<<<(Nin * 32 + 255) / 256, 256>>>(b3, Ws3, Nin);
        k_topk<<<BNUM, 1024>>>(n, kk, p_map2, bs3, p_pm, p_pts);
    }

    k_final<<<BNUM, NH>>>(Wl, bl, out);
}